// round 6
// baseline (speedup 1.0000x reference)
#include <cuda_runtime.h>
#include <cstdint>

#define DIM 128
#define NPAD 50048          // ceil(50000/128)*128
#define NREL 9              // 8 relations + self-loop

// hr[r][node][128] scratch, r in 0..7  (205 MB static device global)
__device__ float g_hr[(size_t)8 * NPAD * DIM];

#define WS_STRIDE 136       // conflict-free B fragment loads
#define SMEM_FLOATS (2 * 128 * WS_STRIDE)
#define SMEM_BYTES (SMEM_FLOATS * 4)   // 139264 B
#define NTHREADS 512

__device__ __forceinline__ uint32_t f2tf32(float f) {
    uint32_t o;
    asm("cvt.rna.tf32.f32 %0, %1;" : "=r"(o) : "f"(f));
    return o;
}

#define MMA_TF32(d, a, b0, b1)                                                  \
    asm volatile("mma.sync.aligned.m16n8k8.row.col.f32.tf32.tf32.f32 "          \
                 "{%0,%1,%2,%3}, {%4,%5,%6,%7}, {%8,%9}, {%0,%1,%2,%3};"        \
                 : "+f"((d)[0]), "+f"((d)[1]), "+f"((d)[2]), "+f"((d)[3])       \
                 : "r"((a)[0]), "r"((a)[1]), "r"((a)[2]), "r"((a)[3]),          \
                   "r"(b0), "r"(b1))

__device__ __forceinline__ void cp16(float* s, const float* g) {
    uint32_t sa = (uint32_t)__cvta_generic_to_shared(s);
    asm volatile("cp.async.cg.shared.global [%0], [%1], 16;" :: "r"(sa), "l"(g));
}

__device__ __forceinline__ void issue_w(float* buf, const float* wr, int tid) {
#pragma unroll
    for (int i = tid; i < 128 * 32; i += NTHREADS) {
        int r = i >> 5, c4 = i & 31;
        cp16(buf + r * WS_STRIDE + c4 * 4, wr + r * DIM + c4 * 4);
    }
    asm volatile("cp.async.commit_group;" ::: "memory");
}

// ---------------------------------------------------------------------------
// GEMM: CTA = 128 node rows x all 9 relations. 512 threads = 16 warps,
// warp tile 16x64. A (X) fragments live in REGISTERS for the whole kernel
// (64 regs/lane), converted to tf32 once. Only W goes through smem.
// ---------------------------------------------------------------------------
__global__ void __launch_bounds__(NTHREADS, 1)
rgcn_gemm_mma(const float* __restrict__ x,
              const float* __restrict__ w,
              const float* __restrict__ sw,
              const float* __restrict__ bias,
              float* __restrict__ out,
              int n_nodes) {
    extern __shared__ float smem[];
    float* Ws0 = smem;                    // [128][WS_STRIDE]
    float* Ws1 = smem + 128 * WS_STRIDE;

    const int tid = threadIdx.x;
    const int wid = tid >> 5, lane = tid & 31;
    const int row0 = blockIdx.x * 128;
    const int wm = (wid & 7) * 16;   // 8 M-blocks of 16 rows
    const int wn = (wid >> 3) * 64;  // 2 N-blocks of 64 cols

    issue_w(Ws0, w, tid);
    issue_w(Ws1, w + DIM * DIM, tid);

    const int lr = lane >> 2;          // 0..7
    const int lk = lane & 3;           // 0..3
    const int lc = (lane & 3) * 2;

    // ---- A fragments: load X rows straight from global, tf32-convert once ----
    const int r_lo = row0 + wm + lr;
    const int r_hi = r_lo + 8;
    const bool vlo = r_lo < n_nodes, vhi = r_hi < n_nodes;
    const float* xlo = x + (size_t)r_lo * DIM;
    const float* xhi = x + (size_t)r_hi * DIM;
    uint32_t A[16][4];
#pragma unroll
    for (int ks = 0; ks < 16; ks++) {
        int k = ks * 8 + lk;
        A[ks][0] = vlo ? f2tf32(xlo[k])     : 0u;
        A[ks][1] = vhi ? f2tf32(xhi[k])     : 0u;
        A[ks][2] = vlo ? f2tf32(xlo[k + 4]) : 0u;
        A[ks][3] = vhi ? f2tf32(xhi[k + 4]) : 0u;
    }

    for (int rel = 0; rel < NREL; ++rel) {
        if (rel == NREL - 1) asm volatile("cp.async.wait_group 0;" ::: "memory");
        else                 asm volatile("cp.async.wait_group 1;" ::: "memory");
        __syncthreads();

        const float* Wb = (rel & 1) ? Ws1 : Ws0;

        float c[8][4];
#pragma unroll
        for (int i = 0; i < 8; i++)
#pragma unroll
            for (int j = 0; j < 4; j++) c[i][j] = 0.0f;

#pragma unroll 4
        for (int ks = 0; ks < 16; ks++) {
            const int k0 = ks * 8;
#pragma unroll
            for (int nt = 0; nt < 8; nt++) {
                const float* wp = Wb + (k0 + lk) * WS_STRIDE + wn + nt * 8 + lr;
                uint32_t b0 = f2tf32(wp[0]);
                uint32_t b1 = f2tf32(wp[4 * WS_STRIDE]);
                MMA_TF32(c[nt], A[ks], b0, b1);
            }
        }

        __syncthreads();   // all warps done reading Wb
        if (rel + 2 < NREL) {
            const float* nw = (rel + 2 < 8) ? (w + (size_t)(rel + 2) * DIM * DIM) : sw;
            issue_w((float*)Wb, nw, tid);
        }

        if (rel < 8) {
            float* base = g_hr + ((size_t)rel * NPAD + row0) * DIM;
#pragma unroll
            for (int nt = 0; nt < 8; nt++) {
                int r = wm + lr;
                int cc = wn + nt * 8 + lc;
                *(float2*)(base + (size_t)r * DIM + cc)       = make_float2(c[nt][0], c[nt][1]);
                *(float2*)(base + (size_t)(r + 8) * DIM + cc) = make_float2(c[nt][2], c[nt][3]);
            }
        } else {
#pragma unroll
            for (int nt = 0; nt < 8; nt++) {
                int r = wm + lr;
                int cc = wn + nt * 8 + lc;
                float b0 = bias[cc], b1 = bias[cc + 1];
                int g0 = row0 + r, g1 = row0 + r + 8;
                if (g0 < n_nodes)
                    *(float2*)(out + (size_t)g0 * DIM + cc) =
                        make_float2(c[nt][0] + b0, c[nt][1] + b1);
                if (g1 < n_nodes)
                    *(float2*)(out + (size_t)g1 * DIM + cc) =
                        make_float2(c[nt][2] + b0, c[nt][3] + b1);
            }
        }
    }
}

// ---------------------------------------------------------------------------
// Scatter: 4 edges per warp (MLP=4 on the 512B gathers), ld.global.cg
// (single-use data, skip L1), red.v4 into out[dst].
// ---------------------------------------------------------------------------
__device__ __forceinline__ float4 ldcg4(const float* p) {
    float4 v;
    asm volatile("ld.global.cg.v4.f32 {%0,%1,%2,%3}, [%4];"
                 : "=f"(v.x), "=f"(v.y), "=f"(v.z), "=f"(v.w) : "l"(p));
    return v;
}

__global__ void rgcn_scatter(const int* __restrict__ ei,
                             const int* __restrict__ et,
                             float* __restrict__ out,
                             int n_edges) {
    int gw = (blockIdx.x * blockDim.x + threadIdx.x) >> 5;
    int lane = threadIdx.x & 31;
    int e0 = gw * 4;
    if (e0 >= n_edges) return;

    int s[4], d[4], r[4];
    int cnt = min(4, n_edges - e0);
#pragma unroll
    for (int j = 0; j < 4; j++) {
        int e = e0 + ((j < cnt) ? j : 0);
        s[j] = ei[e]; d[j] = ei[n_edges + e]; r[j] = et[e];
    }
    float4 v[4];
#pragma unroll
    for (int j = 0; j < 4; j++)
        v[j] = ldcg4(g_hr + ((size_t)r[j] * NPAD + (size_t)s[j]) * DIM + lane * 4);
#pragma unroll
    for (int j = 0; j < 4; j++) {
        if (j < cnt) {
            float* q = out + (size_t)d[j] * DIM + lane * 4;
            asm volatile("red.global.add.v4.f32 [%0], {%1, %2, %3, %4};"
                         :: "l"(q), "f"(v[j].x), "f"(v[j].y), "f"(v[j].z), "f"(v[j].w)
                         : "memory");
        }
    }
}

__global__ void rgcn_relu(float* __restrict__ out, int n4) {
    int i = blockIdx.x * blockDim.x + threadIdx.x;
    if (i < n4) {
        float4 v = ((float4*)out)[i];
        v.x = fmaxf(v.x, 0.0f); v.y = fmaxf(v.y, 0.0f);
        v.z = fmaxf(v.z, 0.0f); v.w = fmaxf(v.w, 0.0f);
        ((float4*)out)[i] = v;
    }
}

// ---------------------------------------------------------------------------
extern "C" void kernel_launch(void* const* d_in, const int* in_sizes, int n_in,
                              void* d_out, int out_size) {
    const float* x    = (const float*)d_in[0];
    const float* w    = (const float*)d_in[1];
    const float* sw   = (const float*)d_in[2];
    const float* bias = (const float*)d_in[3];
    const int* ei = (const int*)d_in[4];
    const int* et = (const int*)d_in[5];

    int n_nodes = in_sizes[0] / DIM;
    int n_edges = in_sizes[5];
    float* out = (float*)d_out;

    cudaFuncSetAttribute(rgcn_gemm_mma, cudaFuncAttributeMaxDynamicSharedMemorySize,
                         SMEM_BYTES);

    int nb = (n_nodes + 127) / 128;
    rgcn_gemm_mma<<<nb, NTHREADS, SMEM_BYTES>>>(x, w, sw, bias, out, n_nodes);

    int n_warps = (n_edges + 3) / 4;
    long long total_threads = (long long)n_warps * 32;
    int blocks = (int)((total_threads + 255) / 256);
    rgcn_scatter<<<blocks, 256>>>(ei, et, out, n_edges);

    int n4 = n_nodes * DIM / 4;
    rgcn_relu<<<(n4 + 255) / 256, 256>>>(out, n4);
}

// round 7
// speedup vs baseline: 1.3114x; 1.3114x over previous
#include <cuda_runtime.h>
#include <cstdint>

#define DIM 128
#define NPAD 50048
#define NREL 9

__device__ float g_hr[(size_t)8 * NPAD * DIM];
// W preconverted to tf32, fragment-major: [rel][ks(16)][nt(16)][lane(32)] float2
__device__ float g_wtf[(size_t)NREL * 16 * 16 * 32 * 2];

#define NTHREADS 256
#define XBLK 132   // floats per (mt,ks) fragment block (128 + 4 pad)
#define XS_FLOATS (8 * 16 * XBLK)             // 16896
#define WB_FLOATS (16 * 16 * 32 * 2)          // 16384
#define SMEM_BYTES ((XS_FLOATS + 2 * WB_FLOATS) * 4)   // 198656

__device__ __forceinline__ uint32_t f2tf32(float f) {
    uint32_t o;
    asm("cvt.rna.tf32.f32 %0, %1;" : "=r"(o) : "f"(f));
    return o;
}

#define MMA_TF32(d, a, b0, b1)                                                  \
    asm volatile("mma.sync.aligned.m16n8k8.row.col.f32.tf32.tf32.f32 "          \
                 "{%0,%1,%2,%3}, {%4,%5,%6,%7}, {%8,%9}, {%0,%1,%2,%3};"        \
                 : "+f"((d)[0]), "+f"((d)[1]), "+f"((d)[2]), "+f"((d)[3])       \
                 : "r"((a)[0]), "r"((a)[1]), "r"((a)[2]), "r"((a)[3]),          \
                   "r"(b0), "r"(b1))

__device__ __forceinline__ void cp16(float* s, const float* g) {
    uint32_t sa = (uint32_t)__cvta_generic_to_shared(s);
    asm volatile("cp.async.cg.shared.global [%0], [%1], 16;" :: "r"(sa), "l"(g));
}

__device__ __forceinline__ void issue_w(float* buf, const float* src, int tid) {
#pragma unroll
    for (int i = tid; i < WB_FLOATS / 4; i += NTHREADS)
        cp16(buf + i * 4, src + i * 4);
    asm volatile("cp.async.commit_group;" ::: "memory");
}

// ---------------------------------------------------------------------------
// Prologue: convert 9 W matrices to tf32, fragment-major.
// b0 = W[k][n], b1 = W[k+4][n]; k = ks*8+(lane&3), n = nt*8+(lane>>2).
// ---------------------------------------------------------------------------
__global__ void conv_w(const float* __restrict__ w, const float* __restrict__ sw) {
    int idx = blockIdx.x * 256 + threadIdx.x;
    if (idx >= NREL * 16 * 16 * 32) return;
    int lane = idx & 31;
    int nt = (idx >> 5) & 15;
    int ks = (idx >> 9) & 15;
    int rel = idx >> 13;
    const float* W = (rel < 8) ? (w + (size_t)rel * DIM * DIM) : sw;
    int k = ks * 8 + (lane & 3);
    int n = nt * 8 + (lane >> 2);
    float2 o;
    o.x = __uint_as_float(f2tf32(W[(size_t)k * DIM + n]));
    o.y = __uint_as_float(f2tf32(W[(size_t)(k + 4) * DIM + n]));
    ((float2*)g_wtf)[idx] = o;
}

// ---------------------------------------------------------------------------
// GEMM: CTA = 128 node rows x 9 relations; 256 thr, 8 warps, warp tile 32x64.
// A fragments: 1 LDS.128 each; B fragments: 1 LDS.64 each; no cvt inner loop.
// ---------------------------------------------------------------------------
__global__ void __launch_bounds__(NTHREADS, 1)
rgcn_gemm_mma(const float* __restrict__ x,
              const float* __restrict__ bias,
              float* __restrict__ out,
              int n_nodes) {
    extern __shared__ float smem[];
    float* Xs  = smem;                         // fragment-major X
    float* Ws0 = smem + XS_FLOATS;
    float* Ws1 = Ws0 + WB_FLOATS;

    const int tid = threadIdx.x;
    const int wid = tid >> 5, lane = tid & 31;
    const int row0 = blockIdx.x * 128;
    const int wmt = (wid & 3) * 2;   // warp's first m-subtile (of 8)
    const int wnt = (wid >> 2) * 8;  // warp's first n-subtile (of 16)

    issue_w(Ws0, g_wtf, tid);
    issue_w(Ws1, g_wtf + WB_FLOATS, tid);

    // ---- X tile fill: fragment-major, tf32-converted once ----
    // element (r, k): mt=r>>4, ks=k>>3, lane=(r&7)*4+(k&3), reg=((r&15)>=8)+((k&7)>=4)*2
#pragma unroll
    for (int i = tid; i < 4096; i += NTHREADS) {
        int r = i >> 5, c4 = i & 31;
        int node = row0 + r;
        float4 v = (node < n_nodes) ? *(const float4*)(x + (size_t)node * DIM + c4 * 4)
                                    : make_float4(0.f, 0.f, 0.f, 0.f);
        int mt = r >> 4, ks = c4 >> 1;
        int reg = (((r & 15) >= 8) ? 1 : 0) + (c4 & 1) * 2;
        float* base = Xs + (mt * 16 + ks) * XBLK + ((r & 7) * 4) * 4 + reg;
        base[0]  = __uint_as_float(f2tf32(v.x));
        base[4]  = __uint_as_float(f2tf32(v.y));
        base[8]  = __uint_as_float(f2tf32(v.z));
        base[12] = __uint_as_float(f2tf32(v.w));
    }

    const int lr = lane >> 2;
    const int lc = (lane & 3) * 2;

    for (int rel = 0; rel < NREL; ++rel) {
        if (rel == NREL - 1) asm volatile("cp.async.wait_group 0;" ::: "memory");
        else                 asm volatile("cp.async.wait_group 1;" ::: "memory");
        __syncthreads();

        const float* Wb = (rel & 1) ? Ws1 : Ws0;

        float c[16][4];
#pragma unroll
        for (int i = 0; i < 16; i++)
#pragma unroll
            for (int j = 0; j < 4; j++) c[i][j] = 0.0f;

        uint32_t Af[2][2][4], Bf[2][8][2];
        // prime ks=0
#pragma unroll
        for (int mt = 0; mt < 2; mt++)
            *(float4*)Af[0][mt] = *(const float4*)(Xs + ((wmt + mt) * 16 + 0) * XBLK + lane * 4);
#pragma unroll
        for (int nt = 0; nt < 8; nt++)
            *(float2*)Bf[0][nt] = *(const float2*)(Wb + ((0 * 16 + wnt + nt) * 32 + lane) * 2);

#pragma unroll
        for (int ks = 0; ks < 16; ks++) {
            const int cur = ks & 1, nxt = cur ^ 1;
            if (ks < 15) {
#pragma unroll
                for (int mt = 0; mt < 2; mt++)
                    *(float4*)Af[nxt][mt] =
                        *(const float4*)(Xs + ((wmt + mt) * 16 + ks + 1) * XBLK + lane * 4);
#pragma unroll
                for (int nt = 0; nt < 8; nt++)
                    *(float2*)Bf[nxt][nt] =
                        *(const float2*)(Wb + (((ks + 1) * 16 + wnt + nt) * 32 + lane) * 2);
            }
#pragma unroll
            for (int nt = 0; nt < 8; nt++) {
                MMA_TF32(c[nt],     Af[cur][0], Bf[cur][nt][0], Bf[cur][nt][1]);
                MMA_TF32(c[8 + nt], Af[cur][1], Bf[cur][nt][0], Bf[cur][nt][1]);
            }
        }

        __syncthreads();
        if (rel + 2 < NREL)
            issue_w((float*)Wb, g_wtf + (size_t)(rel + 2) * WB_FLOATS, tid);

        // epilogue: warp rows = wmt*16 .. ; c[mt*8+nt]
        if (rel < 8) {
            float* base = g_hr + ((size_t)rel * NPAD + row0) * DIM;
#pragma unroll
            for (int mt = 0; mt < 2; mt++)
#pragma unroll
                for (int nt = 0; nt < 8; nt++) {
                    int r = (wmt + mt) * 16 + lr;
                    int cc = (wnt + nt) * 8 + lc;
                    *(float2*)(base + (size_t)r * DIM + cc) =
                        make_float2(c[mt * 8 + nt][0], c[mt * 8 + nt][1]);
                    *(float2*)(base + (size_t)(r + 8) * DIM + cc) =
                        make_float2(c[mt * 8 + nt][2], c[mt * 8 + nt][3]);
                }
        } else {
#pragma unroll
            for (int mt = 0; mt < 2; mt++)
#pragma unroll
                for (int nt = 0; nt < 8; nt++) {
                    int r = (wmt + mt) * 16 + lr;
                    int cc = (wnt + nt) * 8 + lc;
                    float b0 = bias[cc], b1 = bias[cc + 1];
                    int g0 = row0 + r, g1 = row0 + r + 8;
                    if (g0 < n_nodes)
                        *(float2*)(out + (size_t)g0 * DIM + cc) =
                            make_float2(c[mt * 8 + nt][0] + b0, c[mt * 8 + nt][1] + b1);
                    if (g1 < n_nodes)
                        *(float2*)(out + (size_t)g1 * DIM + cc) =
                            make_float2(c[mt * 8 + nt][2] + b0, c[mt * 8 + nt][3] + b1);
                }
        }
    }
}

// ---------------------------------------------------------------------------
// Scatter: 4 edges/warp (MLP=4), ld.global.cg gather, red.v4 into out[dst].
// ---------------------------------------------------------------------------
__device__ __forceinline__ float4 ldcg4(const float* p) {
    float4 v;
    asm volatile("ld.global.cg.v4.f32 {%0,%1,%2,%3}, [%4];"
                 : "=f"(v.x), "=f"(v.y), "=f"(v.z), "=f"(v.w) : "l"(p));
    return v;
}

__global__ void rgcn_scatter(const int* __restrict__ ei,
                             const int* __restrict__ et,
                             float* __restrict__ out,
                             int n_edges) {
    int gw = (blockIdx.x * blockDim.x + threadIdx.x) >> 5;
    int lane = threadIdx.x & 31;
    int e0 = gw * 4;
    if (e0 >= n_edges) return;

    int s[4], d[4], r[4];
    int cnt = min(4, n_edges - e0);
#pragma unroll
    for (int j = 0; j < 4; j++) {
        int e = e0 + ((j < cnt) ? j : 0);
        s[j] = ei[e]; d[j] = ei[n_edges + e]; r[j] = et[e];
    }
    float4 v[4];
#pragma unroll
    for (int j = 0; j < 4; j++)
        v[j] = ldcg4(g_hr + ((size_t)r[j] * NPAD + (size_t)s[j]) * DIM + lane * 4);
#pragma unroll
    for (int j = 0; j < 4; j++) {
        if (j < cnt) {
            float* q = out + (size_t)d[j] * DIM + lane * 4;
            asm volatile("red.global.add.v4.f32 [%0], {%1, %2, %3, %4};"
                         :: "l"(q), "f"(v[j].x), "f"(v[j].y), "f"(v[j].z), "f"(v[j].w)
                         : "memory");
        }
    }
}

__global__ void rgcn_relu(float* __restrict__ out, int n4) {
    int i = blockIdx.x * blockDim.x + threadIdx.x;
    if (i < n4) {
        float4 v = ((float4*)out)[i];
        v.x = fmaxf(v.x, 0.0f); v.y = fmaxf(v.y, 0.0f);
        v.z = fmaxf(v.z, 0.0f); v.w = fmaxf(v.w, 0.0f);
        ((float4*)out)[i] = v;
    }
}

// ---------------------------------------------------------------------------
extern "C" void kernel_launch(void* const* d_in, const int* in_sizes, int n_in,
                              void* d_out, int out_size) {
    const float* x    = (const float*)d_in[0];
    const float* w    = (const float*)d_in[1];
    const float* sw   = (const float*)d_in[2];
    const float* bias = (const float*)d_in[3];
    const int* ei = (const int*)d_in[4];
    const int* et = (const int*)d_in[5];

    int n_nodes = in_sizes[0] / DIM;
    int n_edges = in_sizes[5];
    float* out = (float*)d_out;

    cudaFuncSetAttribute(rgcn_gemm_mma, cudaFuncAttributeMaxDynamicSharedMemorySize,
                         SMEM_BYTES);

    int cw = (NREL * 16 * 16 * 32 + 255) / 256;
    conv_w<<<cw, 256>>>(w, sw);

    int nb = (n_nodes + 127) / 128;
    rgcn_gemm_mma<<<nb, NTHREADS, SMEM_BYTES>>>(x, bias, out, n_nodes);

    int n_warps = (n_edges + 3) / 4;
    long long total_threads = (long long)n_warps * 32;
    int blocks = (int)((total_threads + 255) / 256);
    rgcn_scatter<<<blocks, 256>>>(ei, et, out, n_edges);

    int n4 = n_nodes * DIM / 4;
    rgcn_relu<<<(n4 + 255) / 256, 256>>>(out, n4);
}